// round 5
// baseline (speedup 1.0000x reference)
#include <cuda_runtime.h>

#define SS 48
#define TT 16
#define BB 2
#define NTOT (BB*SS*SS*SS*TT)   // 3,538,944

#define XT 4                    // x-tile per block
#define NXC (XT+4)              // 8 V columns in smem (halo 2)
#define PHY_BLOCKS (BB*SS*(SS/XT))      // 1152
#define SMEM_BYTES (NXC*48*48*4)        // 73728
#define COLBYTES (48*48*4)              // 9216 per column

__device__ double g_phy_part[PHY_BLOCKS];
__device__ double g_mp[PHY_BLOCKS * 4];
__device__ unsigned int g_counter = 0;

__device__ __forceinline__ unsigned int smem_u32(const void* p) {
    return (unsigned int)__cvta_generic_to_shared(p);
}

__device__ __forceinline__ void ld4g(const float* __restrict__ p, int off, float r[4]) {
    float4 v = __ldg(reinterpret_cast<const float4*>(p + off));
    r[0] = v.x; r[1] = v.y; r[2] = v.z; r[3] = v.w;
}
__device__ __forceinline__ void ld4s(const float* p, float r[4]) {
    float4 v = *reinterpret_cast<const float4*>(p);
    r[0] = v.x; r[1] = v.y; r[2] = v.z; r[3] = v.w;
}

// 3-tap coefficients for torch.gradient first derivative (with clamped reads)
__device__ __forceinline__ void coef1(int i, float a[3]) {
    bool lo = (i == 0), hi = (i == SS - 1);
    a[0] = lo ? 0.f  : (hi ? -1.f : -0.5f);
    a[1] = lo ? -1.f : (hi ?  1.f :  0.f );
    a[2] = lo ? 1.f  : (hi ?  0.f :  0.5f);
}
// 5-tap coefficients for grad(grad(f)) (exact composition, with clamped reads)
__device__ __forceinline__ void coef2(int i, float a[5]) {
    float c0 = 0.25f, c1 = 0.f, c2 = -0.5f, c3 = 0.f, c4 = 0.25f;
    if (i == 0)      { c0 = 0.f;   c1 = 0.f;   c2 = 0.5f;   c3 = -1.f;  c4 = 0.5f; }
    if (i == 1)      { c0 = 0.f;   c1 = 0.5f;  c2 = -0.75f; c3 = 0.f;   c4 = 0.25f; }
    if (i == SS - 2) { c0 = 0.25f; c1 = 0.f;   c2 = -0.75f; c3 = 0.5f;  c4 = 0.f; }
    if (i == SS - 1) { c0 = 0.5f;  c1 = -1.f;  c2 = 0.5f;   c3 = 0.f;   c4 = 0.f; }
    a[0] = c0; a[1] = c1; a[2] = c2; a[3] = c3; a[4] = c4;
}

__global__ void k_nop() {}

__global__ void __launch_bounds__(768, 1) k_fused(
    const float* __restrict__ V, const float* __restrict__ P,
    const float* __restrict__ F, const float* __restrict__ RePtr,
    const float* __restrict__ C, const float* __restrict__ X,
    const float* __restrict__ X1, const float* __restrict__ Y,
    const float* __restrict__ XL, float* __restrict__ out)
{
    extern __shared__ float sV[];   // [NXC][48z][48 floats]
    __shared__ __align__(8) unsigned long long mbar;
    __shared__ float ws[24];
    __shared__ float sm2[24][4];

    const int tid = threadIdx.x;
    const int bi  = blockIdx.x;
    const int xt  = bi % (SS / XT);
    const int y   = (bi / (SS / XT)) % SS;
    const int b   = bi / ((SS / XT) * SS);
    const int x0  = xt * XT;
    const int colbase = (b * SS + y) * SS;
    const unsigned int mb = smem_u32(&mbar);

    // ---- init mbarrier, then kick off bulk-async fill of the V tile ----
    if (tid == 0) {
        asm volatile("mbarrier.init.shared.b64 [%0], %1;" :: "r"(mb), "r"(1) : "memory");
    }
    __syncthreads();
    if (tid == 0) {
        asm volatile("mbarrier.arrive.expect_tx.shared.b64 _, [%0], %1;"
                     :: "r"(mb), "r"(SMEM_BYTES) : "memory");
#pragma unroll
        for (int col = 0; col < NXC; col++) {
            int gx = min(max(x0 - 2 + col, 0), SS - 1);
            const float* src = V + (size_t)(colbase + gx) * 2304;
            unsigned int dst = smem_u32(sV) + col * COLBYTES;
            asm volatile(
                "cp.async.bulk.shared::cta.global.mbarrier::complete_tx::bytes [%0], [%1], %2, [%3];"
                :: "r"(dst), "l"(src), "r"(COLBYTES), "r"(mb) : "memory");
        }
    }

    // ================= phase 1: streaming MSE slice (fills TMA latency) =====
    {
        const int g = bi * 768 + tid;   // chunk id (4 t-values)
        const int base = g * 4;
        float ca[4], xa[4], x1a[4], ya[4];
        ld4g(C, base, ca); ld4g(X, base, xa); ld4g(X1, base, x1a); ld4g(Y, base, ya);
        const int tcc = g & 3;
        float prev = (tcc == 0) ? __ldg(XL + (g >> 2)) : __ldg(Y + base - 1);
        float yl[4] = {prev, ya[0], ya[1], ya[2]};

        float m1 = 0.f, m2 = 0.f, t1 = 0.f, t2 = 0.f;
#pragma unroll
        for (int j = 0; j < 4; j++) {
            float a = x1a[j] - ya[j]; m1 += a * a;
            float bv = xa[j]  - ya[j]; m2 += bv * bv;
            float cv = ca[j]  - ya[j]; t2 += cv * cv;
            float dv = yl[j]  - ya[j]; t1 += dv * dv;
        }
#pragma unroll
        for (int off = 16; off; off >>= 1) {
            m1 += __shfl_down_sync(0xffffffffu, m1, off);
            m2 += __shfl_down_sync(0xffffffffu, m2, off);
            t1 += __shfl_down_sync(0xffffffffu, t1, off);
            t2 += __shfl_down_sync(0xffffffffu, t2, off);
        }
        const int w = tid >> 5, l = tid & 31;
        if (l == 0) { sm2[w][0] = m1; sm2[w][1] = m2; sm2[w][2] = t1; sm2[w][3] = t2; }
    }

    // ================= phase 2: all remaining gmem loads + y-partials =======
    const int tc = tid & 3;
    const int z  = (tid >> 2) % 48;
    const int xk = (tid >> 2) / 48;
    const int x  = x0 + xk;
    const int xi = xk + 2;
    const int toff = tc * 4;
    const float Re = __ldg(RePtr);

    const int ym1 = max(y - 1, 0), ym2 = max(y - 2, 0);
    const int yp1 = min(y + 1, SS - 1), yp2 = min(y + 2, SS - 1);
    const int zm1 = max(z - 1, 0), zm2 = max(z - 2, 0);
    const int zp1 = min(z + 1, SS - 1), zp2 = min(z + 2, SS - 1);

    const int sc    = (colbase + x) * SS + z;
    const int s_ym1 = ((b * SS + ym1) * SS + x) * SS + z;
    const int s_ym2 = ((b * SS + ym2) * SS + x) * SS + z;
    const int s_yp1 = ((b * SS + yp1) * SS + x) * SS + z;
    const int s_yp2 = ((b * SS + yp2) * SS + x) * SS + z;

    // coefficients
    float zc1[3], zc2[5], yc1[3], yc2[5], xc1[3], xc2[5];
    coef1(z, zc1); coef2(z, zc2);
    coef1(y, yc1); coef2(y, yc2);
    coef1(x, xc1); coef2(x, xc2);

    // P rows -> dP (rows transient)
    float dP[3][4];
    {
        float pc[4], pzm[4], pzp[4], pxm[4], pxp[4], pym[4], pyp[4];
        ld4g(P, sc * 16 + toff, pc);
        ld4g(P, ((colbase + x) * SS + zm1) * 16 + toff, pzm);
        ld4g(P, ((colbase + x) * SS + zp1) * 16 + toff, pzp);
        ld4g(P, ((colbase + max(x - 1, 0)) * SS + z) * 16 + toff, pxm);
        ld4g(P, ((colbase + min(x + 1, SS - 1)) * SS + z) * 16 + toff, pxp);
        ld4g(P, s_ym1 * 16 + toff, pym);
        ld4g(P, s_yp1 * 16 + toff, pyp);
#pragma unroll
        for (int j = 0; j < 4; j++) {
            dP[0][j] = yc1[0] * pym[j] + yc1[1] * pc[j] + yc1[2] * pyp[j];
            dP[1][j] = xc1[0] * pxm[j] + xc1[1] * pc[j] + xc1[2] * pxp[j];
            dP[2][j] = zc1[0] * pzm[j] + zc1[1] * pc[j] + zc1[2] * pzp[j];
        }
    }

    // F rows
    float fr0[4], fr1[4], fr2[4];
    ld4g(F, sc * 48 + 0  + toff, fr0);
    ld4g(F, sc * 48 + 16 + toff, fr1);
    ld4g(F, sc * 48 + 32 + toff, fr2);

    // y-rows per component -> partial dy and partial lap-y (rows transient).
    // Center-term (cw) contributions are added after the smem tile arrives.
    float pdY[3][4], plY[3][4];
#pragma unroll
    for (int c = 0; c < 3; c++) {
        const int co = c * 16 + toff;
        float rym1[4], rym2[4], ryp1[4], ryp2[4];
        ld4g(V, s_ym1 * 48 + co, rym1);
        ld4g(V, s_ym2 * 48 + co, rym2);
        ld4g(V, s_yp1 * 48 + co, ryp1);
        ld4g(V, s_yp2 * 48 + co, ryp2);
#pragma unroll
        for (int j = 0; j < 4; j++) {
            pdY[c][j] = yc1[0] * rym1[j] + yc1[2] * ryp1[j];
            plY[c][j] = yc2[0] * rym2[j] + yc2[1] * rym1[j]
                      + yc2[3] * ryp1[j] + yc2[4] * ryp2[j];
        }
    }

    // ================= phase 3: wait for V tile, pure smem+FMA ==============
    {
        unsigned int done;
        do {
            asm volatile(
                "{\n\t.reg .pred p;\n\t"
                "mbarrier.try_wait.parity.shared.b64 p, [%1], %2, 0x989680;\n\t"
                "selp.b32 %0, 1, 0, p;\n\t}"
                : "=r"(done) : "r"(mb), "r"(0) : "memory");
        } while (!done);
    }

    float cVv[3][4];
#pragma unroll
    for (int c = 0; c < 3; c++)
        ld4s(&sV[xi * 2304 + z * 48 + c * 16 + toff], cVv[c]);

    float e4[4] = {0.f, 0.f, 0.f, 0.f};
    float local = 0.f;

#pragma unroll
    for (int c = 0; c < 3; c++) {
        const int co = c * 16 + toff;
        float cw[4];
#pragma unroll
        for (int j = 0; j < 4; j++) cw[j] = cVv[c][j];

        float wprev = __shfl_up_sync(0xffffffffu, cw[3], 1);
        float wnext = __shfl_down_sync(0xffffffffu, cw[0], 1);

        float rzm1[4], rzm2[4], rzp1[4], rzp2[4];
        ld4s(&sV[xi * 2304 + zm1 * 48 + co], rzm1);
        ld4s(&sV[xi * 2304 + zm2 * 48 + co], rzm2);
        ld4s(&sV[xi * 2304 + zp1 * 48 + co], rzp1);
        ld4s(&sV[xi * 2304 + zp2 * 48 + co], rzp2);

        float rxm1[4], rxm2[4], rxp1[4], rxp2[4];
        ld4s(&sV[(xi - 1) * 2304 + z * 48 + co], rxm1);
        ld4s(&sV[(xi - 2) * 2304 + z * 48 + co], rxm2);
        ld4s(&sV[(xi + 1) * 2304 + z * 48 + co], rxp1);
        ld4s(&sV[(xi + 2) * 2304 + z * 48 + co], rxp2);

        const float* fr = (c == 0) ? fr0 : (c == 1) ? fr1 : fr2;

#pragma unroll
        for (int j = 0; j < 4; j++) {
            float dyv = pdY[c][j] + yc1[1] * cw[j];
            float dxv = xc1[0] * rxm1[j] + xc1[1] * cw[j] + xc1[2] * rxp1[j];
            float dzv = zc1[0] * rzm1[j] + zc1[1] * cw[j] + zc1[2] * rzp1[j];

            float lap = plY[c][j] + yc2[2] * cw[j];
            lap      += xc2[0] * rxm2[j] + xc2[1] * rxm1[j] + xc2[2] * cw[j]
                      + xc2[3] * rxp1[j] + xc2[4] * rxp2[j];
            lap      += zc2[0] * rzm2[j] + zc2[1] * rzm1[j] + zc2[2] * cw[j]
                      + zc2[3] * rzp1[j] + zc2[4] * rzp2[j];

            float dt;
            if (j == 0)      dt = (tc == 0) ? (cw[1] - cw[0]) : 0.5f * (cw[1] - wprev);
            else if (j == 1) dt = 0.5f * (cw[2] - cw[0]);
            else if (j == 2) dt = 0.5f * (cw[3] - cw[1]);
            else             dt = (tc == 3) ? (cw[3] - cw[2]) : 0.5f * (wnext - cw[2]);

            float e = dt + cVv[1][j] * dxv + cVv[0][j] * dyv + cVv[2][j] * dzv
                    - Re * lap + dP[c][j] + fr[j];
            local += e * e;
            e4[j] += (c == 0) ? dyv : (c == 1) ? dxv : dzv;
        }
    }
#pragma unroll
    for (int j = 0; j < 4; j++) local += e4[j] * e4[j];

#pragma unroll
    for (int off = 16; off; off >>= 1)
        local += __shfl_down_sync(0xffffffffu, local, off);
    if ((tid & 31) == 0) ws[tid >> 5] = local;

    __syncthreads();
    if (tid == 0) {
        float s = 0.f;
        float a = 0.f, b2 = 0.f, c2 = 0.f, d2 = 0.f;
#pragma unroll
        for (int i = 0; i < 24; i++) {
            s += ws[i];
            a += sm2[i][0]; b2 += sm2[i][1]; c2 += sm2[i][2]; d2 += sm2[i][3];
        }
        g_phy_part[bi] = (double)s;
        g_mp[bi * 4 + 0] = (double)a;
        g_mp[bi * 4 + 1] = (double)b2;
        g_mp[bi * 4 + 2] = (double)c2;
        g_mp[bi * 4 + 3] = (double)d2;
    }

    // ---------------- last-block final reduction ----------------
    __shared__ int isLast;
    if (tid == 0) {
        __threadfence();
        unsigned int t = atomicAdd(&g_counter, 1u);
        isLast = (t == PHY_BLOCKS - 1) ? 1 : 0;
    }
    __syncthreads();
    if (isLast) {
        double s0 = 0.0, s1 = 0.0, s2 = 0.0, s3 = 0.0, s4 = 0.0;
        for (int i = tid; i < PHY_BLOCKS; i += 768) {
            s0 += g_phy_part[i];
            s1 += g_mp[i * 4 + 0];
            s2 += g_mp[i * 4 + 1];
            s3 += g_mp[i * 4 + 2];
            s4 += g_mp[i * 4 + 3];
        }
#pragma unroll
        for (int off = 16; off; off >>= 1) {
            s0 += __shfl_down_sync(0xffffffffu, s0, off);
            s1 += __shfl_down_sync(0xffffffffu, s1, off);
            s2 += __shfl_down_sync(0xffffffffu, s2, off);
            s3 += __shfl_down_sync(0xffffffffu, s3, off);
            s4 += __shfl_down_sync(0xffffffffu, s4, off);
        }
        __shared__ double red[24][5];
        const int w = tid >> 5, l = tid & 31;
        if (l == 0) { red[w][0] = s0; red[w][1] = s1; red[w][2] = s2; red[w][3] = s3; red[w][4] = s4; }
        __syncthreads();
        if (tid == 0) {
            double a0 = 0, a1 = 0, a2 = 0, a3 = 0, a4 = 0;
#pragma unroll
            for (int i = 0; i < 24; i++) {
                a0 += red[i][0]; a1 += red[i][1]; a2 += red[i][2]; a3 += red[i][3]; a4 += red[i][4];
            }
            const double invN = 1.0 / (double)NTOT;
            double phy = a0 * invN;
            double m1  = a1 * invN;
            double m2  = a2 * invN;
            double t1  = a3 * invN;
            double t2  = a4 * invN;
            out[0] = (float)m1;
            out[1] = (float)m2;
            out[2] = (float)phy;
            out[3] = (float)((t1 < t2) ? (t2 - t1) : 0.0);
            __threadfence();
            g_counter = 0;   // reset for next graph replay
        }
    }
}

extern "C" void kernel_launch(void* const* d_in, const int* in_sizes, int n_in,
                              void* d_out, int out_size) {
    (void)in_sizes; (void)n_in; (void)out_size;
    const float* C  = (const float*)d_in[0];
    const float* V  = (const float*)d_in[1];
    const float* P  = (const float*)d_in[2];
    const float* X  = (const float*)d_in[3];
    const float* X1 = (const float*)d_in[4];
    const float* F  = (const float*)d_in[5];
    const float* Re = (const float*)d_in[6];
    const float* XL = (const float*)d_in[7];
    const float* Y  = (const float*)d_in[8];
    float* out = (float*)d_out;

    cudaFuncSetAttribute(k_fused, cudaFuncAttributeMaxDynamicSharedMemorySize, SMEM_BYTES);
    k_nop<<<1, 1>>>();   // keeps launch period = 2 so ncu (-s 5) lands on k_fused
    k_fused<<<PHY_BLOCKS, 768, SMEM_BYTES>>>(V, P, F, Re, C, X, X1, Y, XL, out);
}

// round 6
// speedup vs baseline: 1.2815x; 1.2815x over previous
#include <cuda_runtime.h>

#define SS 48
#define TT 16
#define BB 2
#define NTOT (BB*SS*SS*SS*TT)   // 3,538,944

#define XT 2                    // x-tile per block
#define NXC (XT+4)              // 6 V columns in smem (halo 2)
#define THREADS (XT*48*4)       // 384
#define NW (THREADS/32)         // 12 warps
#define PHY_BLOCKS (BB*SS*(SS/XT))      // 2304
#define SMEM_BYTES (NXC*48*48*4)        // 55296
#define COLBYTES (48*48*4)              // 9216 per column

__device__ double g_phy_part[PHY_BLOCKS];
__device__ double g_mp[PHY_BLOCKS * 4];
__device__ unsigned int g_counter = 0;

__device__ __forceinline__ unsigned int smem_u32(const void* p) {
    return (unsigned int)__cvta_generic_to_shared(p);
}

__device__ __forceinline__ void ld4g(const float* __restrict__ p, int off, float r[4]) {
    float4 v = __ldg(reinterpret_cast<const float4*>(p + off));
    r[0] = v.x; r[1] = v.y; r[2] = v.z; r[3] = v.w;
}
__device__ __forceinline__ void ld4s(const float* p, float r[4]) {
    float4 v = *reinterpret_cast<const float4*>(p);
    r[0] = v.x; r[1] = v.y; r[2] = v.z; r[3] = v.w;
}

// 3-tap coefficients for torch.gradient first derivative (with clamped reads)
__device__ __forceinline__ void coef1(int i, float a[3]) {
    bool lo = (i == 0), hi = (i == SS - 1);
    a[0] = lo ? 0.f  : (hi ? -1.f : -0.5f);
    a[1] = lo ? -1.f : (hi ?  1.f :  0.f );
    a[2] = lo ? 1.f  : (hi ?  0.f :  0.5f);
}
// 5-tap coefficients for grad(grad(f)) (exact composition, with clamped reads)
__device__ __forceinline__ void coef2(int i, float a[5]) {
    float c0 = 0.25f, c1 = 0.f, c2 = -0.5f, c3 = 0.f, c4 = 0.25f;
    if (i == 0)      { c0 = 0.f;   c1 = 0.f;   c2 = 0.5f;   c3 = -1.f;  c4 = 0.5f; }
    if (i == 1)      { c0 = 0.f;   c1 = 0.5f;  c2 = -0.75f; c3 = 0.f;   c4 = 0.25f; }
    if (i == SS - 2) { c0 = 0.25f; c1 = 0.f;   c2 = -0.75f; c3 = 0.5f;  c4 = 0.f; }
    if (i == SS - 1) { c0 = 0.5f;  c1 = -1.f;  c2 = 0.5f;   c3 = 0.f;   c4 = 0.f; }
    a[0] = c0; a[1] = c1; a[2] = c2; a[3] = c3; a[4] = c4;
}

__global__ void k_nop() {}

__global__ void __launch_bounds__(THREADS, 2) k_fused(
    const float* __restrict__ V, const float* __restrict__ P,
    const float* __restrict__ F, const float* __restrict__ RePtr,
    const float* __restrict__ C, const float* __restrict__ X,
    const float* __restrict__ X1, const float* __restrict__ Y,
    const float* __restrict__ XL, float* __restrict__ out)
{
    extern __shared__ float sV[];   // [NXC][48z][48 floats]
    __shared__ __align__(8) unsigned long long mbar;
    __shared__ float ws[NW];
    __shared__ float sm2[NW][4];

    const int tid = threadIdx.x;
    const int bi  = blockIdx.x;
    const int xt  = bi % (SS / XT);
    const int y   = (bi / (SS / XT)) % SS;
    const int b   = bi / ((SS / XT) * SS);
    const int x0  = xt * XT;
    const int colbase = (b * SS + y) * SS;
    const unsigned int mb = smem_u32(&mbar);

    // ---- init mbarrier, then kick off bulk-async fill of the V tile ----
    if (tid == 0) {
        asm volatile("mbarrier.init.shared.b64 [%0], %1;" :: "r"(mb), "r"(1) : "memory");
    }
    __syncthreads();
    if (tid == 0) {
        asm volatile("mbarrier.arrive.expect_tx.shared.b64 _, [%0], %1;"
                     :: "r"(mb), "r"(SMEM_BYTES) : "memory");
#pragma unroll
        for (int col = 0; col < NXC; col++) {
            int gx = min(max(x0 - 2 + col, 0), SS - 1);
            const float* src = V + (size_t)(colbase + gx) * 2304;
            unsigned int dst = smem_u32(sV) + col * COLBYTES;
            asm volatile(
                "cp.async.bulk.shared::cta.global.mbarrier::complete_tx::bytes [%0], [%1], %2, [%3];"
                :: "r"(dst), "l"(src), "r"(COLBYTES), "r"(mb) : "memory");
        }
    }

    // ---- while the DMA runs: issue all independent gmem loads + coef math ----
    const int tc = tid & 3;
    const int z  = (tid >> 2) % 48;
    const int xk = (tid >> 2) / 48;
    const int x  = x0 + xk;
    const int xi = xk + 2;
    const int toff = tc * 4;
    const float Re = __ldg(RePtr);

    const int ym1 = max(y - 1, 0), ym2 = max(y - 2, 0);
    const int yp1 = min(y + 1, SS - 1), yp2 = min(y + 2, SS - 1);
    const int zm1 = max(z - 1, 0), zm2 = max(z - 2, 0);
    const int zp1 = min(z + 1, SS - 1), zp2 = min(z + 2, SS - 1);

    const int sc    = (colbase + x) * SS + z;
    const int s_ym1 = ((b * SS + ym1) * SS + x) * SS + z;
    const int s_ym2 = ((b * SS + ym2) * SS + x) * SS + z;
    const int s_yp1 = ((b * SS + yp1) * SS + x) * SS + z;
    const int s_yp2 = ((b * SS + yp2) * SS + x) * SS + z;

    // P rows (7 LDG.128) — independent of smem
    float pc[4], pzm[4], pzp[4], pxm[4], pxp[4], pym[4], pyp[4];
    ld4g(P, sc * 16 + toff, pc);
    ld4g(P, ((colbase + x) * SS + zm1) * 16 + toff, pzm);
    ld4g(P, ((colbase + x) * SS + zp1) * 16 + toff, pzp);
    ld4g(P, ((colbase + max(x - 1, 0)) * SS + z) * 16 + toff, pxm);
    ld4g(P, ((colbase + min(x + 1, SS - 1)) * SS + z) * 16 + toff, pxp);
    ld4g(P, s_ym1 * 16 + toff, pym);
    ld4g(P, s_yp1 * 16 + toff, pyp);

    // F rows (3 LDG.128) — independent of smem
    float fr0[4], fr1[4], fr2[4];
    ld4g(F, sc * 48 + 0  + toff, fr0);
    ld4g(F, sc * 48 + 16 + toff, fr1);
    ld4g(F, sc * 48 + 32 + toff, fr2);

    // stencil coefficients
    float zc1[3], zc2[5], yc1[3], yc2[5], xc1[3], xc2[5];
    coef1(z, zc1); coef2(z, zc2);
    coef1(y, yc1); coef2(y, yc2);
    coef1(x, xc1); coef2(x, xc2);

    // pressure gradient (frees P rows)
    float dP[3][4];
#pragma unroll
    for (int j = 0; j < 4; j++) {
        dP[0][j] = yc1[0] * pym[j] + yc1[1] * pc[j] + yc1[2] * pyp[j];
        dP[1][j] = xc1[0] * pxm[j] + xc1[1] * pc[j] + xc1[2] * pxp[j];
        dP[2][j] = zc1[0] * pzm[j] + zc1[1] * pc[j] + zc1[2] * pzp[j];
    }

    // ---- wait for the V tile ----
    {
        unsigned int done;
        do {
            asm volatile(
                "{\n\t.reg .pred p;\n\t"
                "mbarrier.try_wait.parity.shared.b64 p, [%1], %2, 0x989680;\n\t"
                "selp.b32 %0, 1, 0, p;\n\t}"
                : "=r"(done) : "r"(mb), "r"(0) : "memory");
        } while (!done);
    }

    // center velocities
    float cVv[3][4];
#pragma unroll
    for (int c = 0; c < 3; c++)
        ld4s(&sV[xi * 2304 + z * 48 + c * 16 + toff], cVv[c]);

    float e4[4] = {0.f, 0.f, 0.f, 0.f};
    float local = 0.f;

#pragma unroll
    for (int c = 0; c < 3; c++) {
        const int co = c * 16 + toff;
        float cw[4];
#pragma unroll
        for (int j = 0; j < 4; j++) cw[j] = cVv[c][j];

        float wprev = __shfl_up_sync(0xffffffffu, cw[3], 1);
        float wnext = __shfl_down_sync(0xffffffffu, cw[0], 1);

        float rym1[4], rym2[4], ryp1[4], ryp2[4];
        ld4g(V, s_ym1 * 48 + co, rym1);
        ld4g(V, s_ym2 * 48 + co, rym2);
        ld4g(V, s_yp1 * 48 + co, ryp1);
        ld4g(V, s_yp2 * 48 + co, ryp2);

        float rzm1[4], rzm2[4], rzp1[4], rzp2[4];
        ld4s(&sV[xi * 2304 + zm1 * 48 + co], rzm1);
        ld4s(&sV[xi * 2304 + zm2 * 48 + co], rzm2);
        ld4s(&sV[xi * 2304 + zp1 * 48 + co], rzp1);
        ld4s(&sV[xi * 2304 + zp2 * 48 + co], rzp2);

        float rxm1[4], rxm2[4], rxp1[4], rxp2[4];
        ld4s(&sV[(xi - 1) * 2304 + z * 48 + co], rxm1);
        ld4s(&sV[(xi - 2) * 2304 + z * 48 + co], rxm2);
        ld4s(&sV[(xi + 1) * 2304 + z * 48 + co], rxp1);
        ld4s(&sV[(xi + 2) * 2304 + z * 48 + co], rxp2);

        const float* fr = (c == 0) ? fr0 : (c == 1) ? fr1 : fr2;

#pragma unroll
        for (int j = 0; j < 4; j++) {
            float dyv = yc1[0] * rym1[j] + yc1[1] * cw[j] + yc1[2] * ryp1[j];
            float dxv = xc1[0] * rxm1[j] + xc1[1] * cw[j] + xc1[2] * rxp1[j];
            float dzv = zc1[0] * rzm1[j] + zc1[1] * cw[j] + zc1[2] * rzp1[j];

            float lap = yc2[0] * rym2[j] + yc2[1] * rym1[j] + yc2[2] * cw[j]
                      + yc2[3] * ryp1[j] + yc2[4] * ryp2[j];
            lap      += xc2[0] * rxm2[j] + xc2[1] * rxm1[j] + xc2[2] * cw[j]
                      + xc2[3] * rxp1[j] + xc2[4] * rxp2[j];
            lap      += zc2[0] * rzm2[j] + zc2[1] * rzm1[j] + zc2[2] * cw[j]
                      + zc2[3] * rzp1[j] + zc2[4] * rzp2[j];

            float dt;
            if (j == 0)      dt = (tc == 0) ? (cw[1] - cw[0]) : 0.5f * (cw[1] - wprev);
            else if (j == 1) dt = 0.5f * (cw[2] - cw[0]);
            else if (j == 2) dt = 0.5f * (cw[3] - cw[1]);
            else             dt = (tc == 3) ? (cw[3] - cw[2]) : 0.5f * (wnext - cw[2]);

            float e = dt + cVv[1][j] * dxv + cVv[0][j] * dyv + cVv[2][j] * dzv
                    - Re * lap + dP[c][j] + fr[j];
            local += e * e;
            e4[j] += (c == 0) ? dyv : (c == 1) ? dxv : dzv;
        }
    }
#pragma unroll
    for (int j = 0; j < 4; j++) local += e4[j] * e4[j];

#pragma unroll
    for (int off = 16; off; off >>= 1)
        local += __shfl_down_sync(0xffffffffu, local, off);
    if ((tid & 31) == 0) ws[tid >> 5] = local;

    // ---------------- streaming MSE slice for this block ----------------
    {
        const int g = bi * THREADS + tid;   // chunk id (4 t-values)
        const int base = g * 4;
        float ca[4], xa[4], x1a[4], ya[4];
        ld4g(C, base, ca); ld4g(X, base, xa); ld4g(X1, base, x1a); ld4g(Y, base, ya);
        const int tcc = g & 3;
        float prev = (tcc == 0) ? __ldg(XL + (g >> 2)) : __ldg(Y + base - 1);
        float yl[4] = {prev, ya[0], ya[1], ya[2]};

        float m1 = 0.f, m2 = 0.f, t1 = 0.f, t2 = 0.f;
#pragma unroll
        for (int j = 0; j < 4; j++) {
            float a = x1a[j] - ya[j]; m1 += a * a;
            float bv = xa[j]  - ya[j]; m2 += bv * bv;
            float cv = ca[j]  - ya[j]; t2 += cv * cv;
            float dv = yl[j]  - ya[j]; t1 += dv * dv;
        }
#pragma unroll
        for (int off = 16; off; off >>= 1) {
            m1 += __shfl_down_sync(0xffffffffu, m1, off);
            m2 += __shfl_down_sync(0xffffffffu, m2, off);
            t1 += __shfl_down_sync(0xffffffffu, t1, off);
            t2 += __shfl_down_sync(0xffffffffu, t2, off);
        }
        const int w = tid >> 5, l = tid & 31;
        if (l == 0) { sm2[w][0] = m1; sm2[w][1] = m2; sm2[w][2] = t1; sm2[w][3] = t2; }
    }

    __syncthreads();
    if (tid == 0) {
        float s = 0.f;
        float a = 0.f, b2 = 0.f, c2 = 0.f, d2 = 0.f;
#pragma unroll
        for (int i = 0; i < NW; i++) {
            s += ws[i];
            a += sm2[i][0]; b2 += sm2[i][1]; c2 += sm2[i][2]; d2 += sm2[i][3];
        }
        g_phy_part[bi] = (double)s;
        g_mp[bi * 4 + 0] = (double)a;
        g_mp[bi * 4 + 1] = (double)b2;
        g_mp[bi * 4 + 2] = (double)c2;
        g_mp[bi * 4 + 3] = (double)d2;
    }

    // ---------------- last-block final reduction ----------------
    __shared__ int isLast;
    if (tid == 0) {
        __threadfence();
        unsigned int t = atomicAdd(&g_counter, 1u);
        isLast = (t == PHY_BLOCKS - 1) ? 1 : 0;
    }
    __syncthreads();
    if (isLast) {
        double s0 = 0.0, s1 = 0.0, s2 = 0.0, s3 = 0.0, s4 = 0.0;
        for (int i = tid; i < PHY_BLOCKS; i += THREADS) {
            s0 += g_phy_part[i];
            s1 += g_mp[i * 4 + 0];
            s2 += g_mp[i * 4 + 1];
            s3 += g_mp[i * 4 + 2];
            s4 += g_mp[i * 4 + 3];
        }
#pragma unroll
        for (int off = 16; off; off >>= 1) {
            s0 += __shfl_down_sync(0xffffffffu, s0, off);
            s1 += __shfl_down_sync(0xffffffffu, s1, off);
            s2 += __shfl_down_sync(0xffffffffu, s2, off);
            s3 += __shfl_down_sync(0xffffffffu, s3, off);
            s4 += __shfl_down_sync(0xffffffffu, s4, off);
        }
        __shared__ double red[NW][5];
        const int w = tid >> 5, l = tid & 31;
        if (l == 0) { red[w][0] = s0; red[w][1] = s1; red[w][2] = s2; red[w][3] = s3; red[w][4] = s4; }
        __syncthreads();
        if (tid == 0) {
            double a0 = 0, a1 = 0, a2 = 0, a3 = 0, a4 = 0;
#pragma unroll
            for (int i = 0; i < NW; i++) {
                a0 += red[i][0]; a1 += red[i][1]; a2 += red[i][2]; a3 += red[i][3]; a4 += red[i][4];
            }
            const double invN = 1.0 / (double)NTOT;
            double phy = a0 * invN;
            double m1  = a1 * invN;
            double m2  = a2 * invN;
            double t1  = a3 * invN;
            double t2  = a4 * invN;
            out[0] = (float)m1;
            out[1] = (float)m2;
            out[2] = (float)phy;
            out[3] = (float)((t1 < t2) ? (t2 - t1) : 0.0);
            __threadfence();
            g_counter = 0;   // reset for next graph replay
        }
    }
}

extern "C" void kernel_launch(void* const* d_in, const int* in_sizes, int n_in,
                              void* d_out, int out_size) {
    (void)in_sizes; (void)n_in; (void)out_size;
    const float* C  = (const float*)d_in[0];
    const float* V  = (const float*)d_in[1];
    const float* P  = (const float*)d_in[2];
    const float* X  = (const float*)d_in[3];
    const float* X1 = (const float*)d_in[4];
    const float* F  = (const float*)d_in[5];
    const float* Re = (const float*)d_in[6];
    const float* XL = (const float*)d_in[7];
    const float* Y  = (const float*)d_in[8];
    float* out = (float*)d_out;

    cudaFuncSetAttribute(k_fused, cudaFuncAttributeMaxDynamicSharedMemorySize, SMEM_BYTES);
    k_nop<<<1, 1>>>();   // keeps launch period = 2 so ncu (-s 5) lands on k_fused
    k_fused<<<PHY_BLOCKS, THREADS, SMEM_BYTES>>>(V, P, F, Re, C, X, X1, Y, XL, out);
}